// round 1
// baseline (speedup 1.0000x reference)
#include <cuda_runtime.h>
#include <cstdint>

#define N_MAX   50048
#define IN_C    256
#define HID     16
#define HEADS   8
#define F1      128     // HEADS*HID
#define OUT_C   32
#define SLOPE   0.2f

// ---------------- scratch (device globals; no allocation allowed) ----------
__device__ float    g_h1  [(size_t)N_MAX * F1];
__device__ float    g_out1[(size_t)N_MAX * F1];
__device__ float    g_als1[(size_t)N_MAX * HEADS];
__device__ float    g_ald1[(size_t)N_MAX * HEADS];
__device__ unsigned g_m1  [(size_t)N_MAX * HEADS];
__device__ float    g_den1[(size_t)N_MAX * HEADS];
__device__ float    g_h2  [(size_t)N_MAX * OUT_C];
__device__ float    g_out2[(size_t)N_MAX * OUT_C];
__device__ float    g_als2[N_MAX];
__device__ float    g_ald2[N_MAX];
__device__ unsigned g_m2  [N_MAX];
__device__ float    g_den2[N_MAX];
__device__ int      g_is64;

// --------------- helpers ---------------------------------------------------
__device__ __forceinline__ unsigned fenc(float f) {
    unsigned b = __float_as_uint(f);
    return (b & 0x80000000u) ? ~b : (b | 0x80000000u);
}
__device__ __forceinline__ float fdec(unsigned u) {
    return __uint_as_float((u & 0x80000000u) ? (u ^ 0x80000000u) : ~u);
}
__device__ __forceinline__ float lrelu(float v) {
    return v > 0.f ? v : SLOPE * v;
}
__device__ __forceinline__ void get_edge(const void* ei, int e, int E, int& s, int& d) {
    if (e < E) {
        if (g_is64) {
            const long long* p = (const long long*)ei;
            s = (int)p[e]; d = (int)p[(size_t)E + e];
        } else {
            const int* p = (const int*)ei;
            s = p[e]; d = p[(size_t)E + e];
        }
    } else {
        s = d = e - E;
    }
}
__device__ __forceinline__ void red_add_v4(float* p, float x, float y, float z, float w) {
    asm volatile("red.global.add.v4.f32 [%0], {%1,%2,%3,%4};"
                 :: "l"(p), "f"(x), "f"(y), "f"(z), "f"(w) : "memory");
}

// --------------- dtype detection: int64 arrays have zero hi-words ----------
__global__ void detect_kernel(const int* ei) {
    if (threadIdx.x == 0 && blockIdx.x == 0) {
        int all0 = 1;
        for (int i = 1; i < 64; i += 2) all0 &= (ei[i] == 0);
        g_is64 = all0;
    }
}

// --------------- per-call zeroing (graph replays!) --------------------------
__global__ void zero_kernel(int n) {
    int i = blockIdx.x * blockDim.x + threadIdx.x;
    if (i < n * F1)    g_out1[i] = 0.f;
    if (i < n * OUT_C) g_out2[i] = 0.f;
    if (i < n * HEADS) { g_m1[i] = 0u; g_den1[i] = 0.f; }
    if (i < n)         { g_m2[i] = 0u; g_den2[i] = 0.f; }
}

// --------------- GEMM1: h1 = x[M,256] @ W1[256,128] ------------------------
#define BM 128
#define BN 128
#define BK 16
#define TM 8
#define TN 8
__global__ __launch_bounds__(256) void gemm1_kernel(const float* __restrict__ A,
                                                    const float* __restrict__ B, int M) {
    __shared__ float As[BK][BM];
    __shared__ float Bs[BK][BN];
    int tid = threadIdx.x;
    int tr = tid >> 4, tc = tid & 15;
    float acc[TM][TN] = {};
    int rowA0 = blockIdx.x * BM;

    int aRow = tid >> 2;          // 0..63
    int aCol = (tid & 3) << 2;    // 0,4,8,12
    int bRow = tid >> 5;          // 0..7
    int bCol = (tid & 31) << 2;   // 0..124

    for (int k0 = 0; k0 < IN_C; k0 += BK) {
#pragma unroll
        for (int r = 0; r < 2; r++) {
            int row = rowA0 + aRow + r * 64;
            float4 v = make_float4(0.f, 0.f, 0.f, 0.f);
            if (row < M) v = *(const float4*)(A + (size_t)row * IN_C + k0 + aCol);
            As[aCol + 0][aRow + r * 64] = v.x;
            As[aCol + 1][aRow + r * 64] = v.y;
            As[aCol + 2][aRow + r * 64] = v.z;
            As[aCol + 3][aRow + r * 64] = v.w;
        }
#pragma unroll
        for (int r = 0; r < 2; r++) {
            float4 v = *(const float4*)(B + (size_t)(k0 + bRow + r * 8) * F1 + bCol);
            *(float4*)&Bs[bRow + r * 8][bCol] = v;
        }
        __syncthreads();
#pragma unroll
        for (int k = 0; k < BK; k++) {
            float rm[TM], rn[TN];
#pragma unroll
            for (int i = 0; i < TM; i++) rm[i] = As[k][tr * TM + i];
#pragma unroll
            for (int j = 0; j < TN; j++) rn[j] = Bs[k][tc * TN + j];
#pragma unroll
            for (int i = 0; i < TM; i++)
#pragma unroll
                for (int j = 0; j < TN; j++)
                    acc[i][j] += rm[i] * rn[j];
        }
        __syncthreads();
    }
#pragma unroll
    for (int i = 0; i < TM; i++) {
        int row = rowA0 + tr * TM + i;
        if (row < M) {
#pragma unroll
            for (int j = 0; j < TN; j += 4) {
                float4 v = make_float4(acc[i][j], acc[i][j + 1], acc[i][j + 2], acc[i][j + 3]);
                *(float4*)(g_h1 + (size_t)row * F1 + tc * TN + j) = v;
            }
        }
    }
}

// --------------- layer-1 attention logits per node --------------------------
__global__ void node1_kernel(const float* __restrict__ a_src,
                             const float* __restrict__ a_dst, int n) {
    int idx = blockIdx.x * blockDim.x + threadIdx.x;  // node*8+head
    if (idx >= n * HEADS) return;
    int node = idx >> 3, h = idx & 7;
    const float* hp = g_h1 + (size_t)node * F1 + h * HID;
    const float* as = a_src + h * HID;
    const float* ad = a_dst + h * HID;
    float s = 0.f, d = 0.f;
#pragma unroll
    for (int c = 0; c < HID; c++) { float v = hp[c]; s += v * as[c]; d += v * ad[c]; }
    g_als1[idx] = s; g_ald1[idx] = d;
}

// --------------- layer-1 edge passes ----------------------------------------
__global__ void emax1_kernel(const void* ei, int E, int Et) {
    int e = blockIdx.x * blockDim.x + threadIdx.x;
    if (e >= Et) return;
    int s, d; get_edge(ei, e, E, s, d);
#pragma unroll
    for (int h = 0; h < HEADS; h++) {
        float v = lrelu(g_als1[s * HEADS + h] + g_ald1[d * HEADS + h]);
        atomicMax(&g_m1[d * HEADS + h], fenc(v));
    }
}
__global__ void esum1_kernel(const void* ei, int E, int Et) {
    int e = blockIdx.x * blockDim.x + threadIdx.x;
    if (e >= Et) return;
    int s, d; get_edge(ei, e, E, s, d);
#pragma unroll
    for (int h = 0; h < HEADS; h++) {
        float v = lrelu(g_als1[s * HEADS + h] + g_ald1[d * HEADS + h]);
        float m = fdec(g_m1[d * HEADS + h]);
        atomicAdd(&g_den1[d * HEADS + h], __expf(v - m));
    }
}
__global__ __launch_bounds__(256) void escatter1_kernel(const void* ei, int E, int Et) {
    int warp = (blockIdx.x * blockDim.x + threadIdx.x) >> 5;
    int lane = threadIdx.x & 31;
    if (warp >= Et) return;
    int s, d; get_edge(ei, warp, E, s, d);
    int h = lane >> 2;   // 4 lanes per head (16 floats)
    float v = lrelu(g_als1[s * HEADS + h] + g_ald1[d * HEADS + h]);
    float m = fdec(g_m1[d * HEADS + h]);
    float alpha = __expf(v - m) / (g_den1[d * HEADS + h] + 1e-16f);
    float4 hv = *(const float4*)(g_h1 + (size_t)s * F1 + lane * 4);
    float* op = g_out1 + (size_t)d * F1 + lane * 4;
    red_add_v4(op, hv.x * alpha, hv.y * alpha, hv.z * alpha, hv.w * alpha);
}

// --------------- bias + relu -------------------------------------------------
__global__ void relu1_kernel(const float* __restrict__ b1, int n) {
    int i = blockIdx.x * blockDim.x + threadIdx.x;
    if (i < n * F1) {
        float v = g_out1[i] + b1[i & (F1 - 1)];
        g_out1[i] = v > 0.f ? v : 0.f;
    }
}

// --------------- GEMM2: h2 = out1[M,128] @ W2[128,32] -----------------------
__global__ __launch_bounds__(256) void gemm2_kernel(const float* __restrict__ W2, int n) {
    __shared__ float Ws[F1 * OUT_C];
    int tid = threadIdx.x;
    for (int i = tid; i < F1 * OUT_C; i += blockDim.x) Ws[i] = W2[i];
    __syncthreads();
    int warp = (blockIdx.x * blockDim.x + tid) >> 5;
    int lane = tid & 31;
    if (warp >= n) return;
    const float* hp = g_out1 + (size_t)warp * F1;
    float acc = 0.f;
#pragma unroll 8
    for (int k = 0; k < F1; k++) acc += hp[k] * Ws[k * OUT_C + lane];
    g_h2[(size_t)warp * OUT_C + lane] = acc;
}

// --------------- layer-2 attention logits ------------------------------------
__global__ void node2_kernel(const float* __restrict__ a_s,
                             const float* __restrict__ a_d, int n) {
    int node = blockIdx.x * blockDim.x + threadIdx.x;
    if (node >= n) return;
    const float* hp = g_h2 + (size_t)node * OUT_C;
    float s = 0.f, d = 0.f;
#pragma unroll
    for (int c = 0; c < OUT_C; c++) { float v = hp[c]; s += v * a_s[c]; d += v * a_d[c]; }
    g_als2[node] = s; g_ald2[node] = d;
}

// --------------- layer-2 edge passes ------------------------------------------
__global__ void emax2_kernel(const void* ei, int E, int Et) {
    int e = blockIdx.x * blockDim.x + threadIdx.x;
    if (e >= Et) return;
    int s, d; get_edge(ei, e, E, s, d);
    float v = lrelu(g_als2[s] + g_ald2[d]);
    atomicMax(&g_m2[d], fenc(v));
}
__global__ void esum2_kernel(const void* ei, int E, int Et) {
    int e = blockIdx.x * blockDim.x + threadIdx.x;
    if (e >= Et) return;
    int s, d; get_edge(ei, e, E, s, d);
    float v = lrelu(g_als2[s] + g_ald2[d]);
    atomicAdd(&g_den2[d], __expf(v - fdec(g_m2[d])));
}
__global__ __launch_bounds__(256) void escatter2_kernel(const void* ei, int E, int Et) {
    int gt = blockIdx.x * blockDim.x + threadIdx.x;
    int e = gt >> 3; int l8 = gt & 7;   // 8 threads per edge, float4 each
    if (e >= Et) return;
    int s, d; get_edge(ei, e, E, s, d);
    float v = lrelu(g_als2[s] + g_ald2[d]);
    float alpha = __expf(v - fdec(g_m2[d])) / (g_den2[d] + 1e-16f);
    float4 hv = *(const float4*)(g_h2 + (size_t)s * OUT_C + l8 * 4);
    float* op = g_out2 + (size_t)d * OUT_C + l8 * 4;
    red_add_v4(op, hv.x * alpha, hv.y * alpha, hv.z * alpha, hv.w * alpha);
}

// --------------- bias + log_softmax -------------------------------------------
__global__ void final_kernel(const float* __restrict__ b2, float* __restrict__ out, int n) {
    int warp = (blockIdx.x * blockDim.x + threadIdx.x) >> 5;
    int lane = threadIdx.x & 31;   // 32 lanes == 32 classes
    if (warp >= n) return;
    float v = g_out2[(size_t)warp * OUT_C + lane] + b2[lane];
    float mx = v;
#pragma unroll
    for (int o = 16; o; o >>= 1) mx = fmaxf(mx, __shfl_xor_sync(0xffffffffu, mx, o));
    float ex = __expf(v - mx);
    float sum = ex;
#pragma unroll
    for (int o = 16; o; o >>= 1) sum += __shfl_xor_sync(0xffffffffu, sum, o);
    out[(size_t)warp * OUT_C + lane] = v - mx - logf(sum);
}

// --------------- launcher ------------------------------------------------------
extern "C" void kernel_launch(void* const* d_in, const int* in_sizes, int n_in,
                              void* d_out, int out_size) {
    const float* x   = (const float*)d_in[0];
    const void*  ei  = d_in[1];
    const float* W1  = (const float*)d_in[2];
    const float* as1 = (const float*)d_in[3];
    const float* ad1 = (const float*)d_in[4];
    const float* b1  = (const float*)d_in[5];
    const float* W2  = (const float*)d_in[6];
    const float* as2 = (const float*)d_in[7];
    const float* ad2 = (const float*)d_in[8];
    const float* b2  = (const float*)d_in[9];

    int n  = in_sizes[0] / IN_C;
    int E  = in_sizes[1] / 2;
    int Et = E + n;

    detect_kernel<<<1, 32>>>((const int*)ei);
    zero_kernel<<<(n * F1 + 255) / 256, 256>>>(n);

    gemm1_kernel<<<(n + BM - 1) / BM, 256>>>(x, W1, n);
    node1_kernel<<<(n * HEADS + 255) / 256, 256>>>(as1, ad1, n);
    emax1_kernel<<<(Et + 255) / 256, 256>>>(ei, E, Et);
    esum1_kernel<<<(Et + 255) / 256, 256>>>(ei, E, Et);
    {
        long long threads = (long long)Et * 32;
        escatter1_kernel<<<(unsigned)((threads + 255) / 256), 256>>>(ei, E, Et);
    }
    relu1_kernel<<<(n * F1 + 255) / 256, 256>>>(b1, n);

    gemm2_kernel<<<(n + 7) / 8, 256>>>(W2, n);
    node2_kernel<<<(n + 255) / 256, 256>>>(as2, ad2, n);
    emax2_kernel<<<(Et + 255) / 256, 256>>>(ei, E, Et);
    esum2_kernel<<<(Et + 255) / 256, 256>>>(ei, E, Et);
    {
        long long threads = (long long)Et * 8;
        escatter2_kernel<<<(unsigned)((threads + 255) / 256), 256>>>(ei, E, Et);
    }
    final_kernel<<<(n * 32 + 255) / 256, 256>>>(b2, (float*)d_out, n);
}

// round 2
// speedup vs baseline: 1.8630x; 1.8630x over previous
#include <cuda_runtime.h>
#include <cstdint>

#define IN_C    256
#define HID     16
#define HEADS   8
#define F1      128     // HEADS*HID
#define OUT_C   32
#define SLOPE   0.2f
#define N_MAX   50048
#define E_MAX   851968  // E + N headroom

// ---------------- scratch (device globals; no allocation allowed) ----------
__device__ int2     g_edges  [E_MAX];
__device__ int      g_csr_src[E_MAX];
__device__ int      g_cnt    [N_MAX];
__device__ int      g_rowptr [N_MAX];
__device__ int      g_cursor [N_MAX];
__device__ int      g_bsum   [64];
__device__ float    g_h1  [(size_t)N_MAX * F1];
__device__ float    g_out1[(size_t)N_MAX * F1];
__device__ float    g_als1[(size_t)N_MAX * HEADS];
__device__ float    g_ald1[(size_t)N_MAX * HEADS];
__device__ float    g_h2  [(size_t)N_MAX * OUT_C];
__device__ float    g_als2[N_MAX];
__device__ float    g_ald2[N_MAX];
__device__ int      g_is64;

__device__ __forceinline__ float lrelu(float v) { return v > 0.f ? v : SLOPE * v; }

// --------------- dtype detection: int64 arrays have zero hi-words ----------
__global__ void detect_kernel(const int* ei) {
    if (threadIdx.x == 0 && blockIdx.x == 0) {
        int all0 = 1;
        for (int i = 1; i < 64; i += 2) all0 &= (ei[i] == 0);
        g_is64 = all0;
    }
}

__global__ void zero_cnt_kernel(int n) {
    int i = blockIdx.x * blockDim.x + threadIdx.x;
    if (i < n) g_cnt[i] = 0;
}

// --------------- edge decode + degree histogram ------------------------------
__global__ void prep_kernel(const void* ei, int E, int Et) {
    int e = blockIdx.x * blockDim.x + threadIdx.x;
    if (e >= Et) return;
    int s, d;
    if (e < E) {
        if (g_is64) {
            const long long* p = (const long long*)ei;
            s = (int)p[e]; d = (int)p[(size_t)E + e];
        } else {
            const int* p = (const int*)ei;
            s = p[e]; d = p[(size_t)E + e];
        }
    } else {
        s = d = e - E;
    }
    g_edges[e] = make_int2(s, d);
    atomicAdd(&g_cnt[d], 1);
}

// --------------- 3-kernel exclusive scan of g_cnt ----------------------------
__global__ __launch_bounds__(1024) void scan1_kernel(int n) {
    __shared__ int sm[1024];
    int i = blockIdx.x * 1024 + threadIdx.x;
    int v = (i < n) ? g_cnt[i] : 0;
    sm[threadIdx.x] = v;
    __syncthreads();
    for (int off = 1; off < 1024; off <<= 1) {
        int t = (threadIdx.x >= off) ? sm[threadIdx.x - off] : 0;
        __syncthreads();
        sm[threadIdx.x] += t;
        __syncthreads();
    }
    if (i < n) g_rowptr[i] = sm[threadIdx.x];      // inclusive (block-local)
    if (threadIdx.x == 1023) g_bsum[blockIdx.x] = sm[1023];
}
__global__ void scan2_kernel(int nb) {
    __shared__ int sm[64];
    int v = (threadIdx.x < nb) ? g_bsum[threadIdx.x] : 0;
    sm[threadIdx.x] = v;
    __syncthreads();
    for (int off = 1; off < 64; off <<= 1) {
        int t = (threadIdx.x >= off) ? sm[threadIdx.x - off] : 0;
        __syncthreads();
        sm[threadIdx.x] += t;
        __syncthreads();
    }
    g_bsum[threadIdx.x] = sm[threadIdx.x];
}
__global__ void scan3_kernel(int n) {
    int i = blockIdx.x * blockDim.x + threadIdx.x;
    if (i >= n) return;
    int b = i >> 10;
    int incl = g_rowptr[i] + (b ? g_bsum[b - 1] : 0);
    int start = incl - g_cnt[i];
    g_rowptr[i] = start;
    g_cursor[i] = start;
}

// --------------- bucket edges by dst ----------------------------------------
__global__ void bucket_kernel(int Et) {
    int e = blockIdx.x * blockDim.x + threadIdx.x;
    if (e >= Et) return;
    int2 sd = g_edges[e];
    int pos = atomicAdd(&g_cursor[sd.y], 1);
    g_csr_src[pos] = sd.x;
}

// --------------- GEMM1: h1 = x[M,256] @ W1[256,128] ------------------------
#define BM 128
#define BK 16
#define TM 8
#define TN 8
__global__ __launch_bounds__(256) void gemm1_kernel(const float* __restrict__ A,
                                                    const float* __restrict__ B, int M) {
    __shared__ float As[BK][BM];
    __shared__ float Bs[BK][F1];
    int tid = threadIdx.x;
    int tr = tid >> 4, tc = tid & 15;
    float acc[TM][TN] = {};
    int rowA0 = blockIdx.x * BM;

    int aRow = tid >> 2;          // 0..63
    int aCol = (tid & 3) << 2;    // 0,4,8,12
    int bRow = tid >> 5;          // 0..7
    int bCol = (tid & 31) << 2;   // 0..124

    for (int k0 = 0; k0 < IN_C; k0 += BK) {
#pragma unroll
        for (int r = 0; r < 2; r++) {
            int row = rowA0 + aRow + r * 64;
            float4 v = make_float4(0.f, 0.f, 0.f, 0.f);
            if (row < M) v = *(const float4*)(A + (size_t)row * IN_C + k0 + aCol);
            As[aCol + 0][aRow + r * 64] = v.x;
            As[aCol + 1][aRow + r * 64] = v.y;
            As[aCol + 2][aRow + r * 64] = v.z;
            As[aCol + 3][aRow + r * 64] = v.w;
        }
#pragma unroll
        for (int r = 0; r < 2; r++) {
            float4 v = *(const float4*)(B + (size_t)(k0 + bRow + r * 8) * F1 + bCol);
            *(float4*)&Bs[bRow + r * 8][bCol] = v;
        }
        __syncthreads();
#pragma unroll
        for (int k = 0; k < BK; k++) {
            float rm[TM], rn[TN];
#pragma unroll
            for (int i = 0; i < TM; i++) rm[i] = As[k][tr * TM + i];
#pragma unroll
            for (int j = 0; j < TN; j++) rn[j] = Bs[k][tc * TN + j];
#pragma unroll
            for (int i = 0; i < TM; i++)
#pragma unroll
                for (int j = 0; j < TN; j++)
                    acc[i][j] += rm[i] * rn[j];
        }
        __syncthreads();
    }
#pragma unroll
    for (int i = 0; i < TM; i++) {
        int row = rowA0 + tr * TM + i;
        if (row < M) {
#pragma unroll
            for (int j = 0; j < TN; j += 4) {
                float4 v = make_float4(acc[i][j], acc[i][j + 1], acc[i][j + 2], acc[i][j + 3]);
                *(float4*)(g_h1 + (size_t)row * F1 + tc * TN + j) = v;
            }
        }
    }
}

// --------------- layer-1 attention logits: warp per node ---------------------
__global__ __launch_bounds__(256) void node1_kernel(const float* __restrict__ a_src,
                                                    const float* __restrict__ a_dst, int n) {
    __shared__ float ssrc[F1], sdst[F1];
    int tid = threadIdx.x;
    if (tid < F1) { ssrc[tid] = a_src[tid]; sdst[tid] = a_dst[tid]; }
    __syncthreads();
    int warp = tid >> 5, lane = tid & 31;
    int node = blockIdx.x * 8 + warp;
    if (node >= n) return;
    float4 hv = *(const float4*)(g_h1 + (size_t)node * F1 + lane * 4);
    float4 a  = *(const float4*)(ssrc + lane * 4);
    float4 b  = *(const float4*)(sdst + lane * 4);
    float s = hv.x * a.x + hv.y * a.y + hv.z * a.z + hv.w * a.w;
    float d = hv.x * b.x + hv.y * b.y + hv.z * b.z + hv.w * b.w;
    s += __shfl_xor_sync(0xffffffffu, s, 1);
    s += __shfl_xor_sync(0xffffffffu, s, 2);
    d += __shfl_xor_sync(0xffffffffu, d, 1);
    d += __shfl_xor_sync(0xffffffffu, d, 2);
    if ((lane & 3) == 0) {
        g_als1[node * HEADS + (lane >> 2)] = s;
        g_ald1[node * HEADS + (lane >> 2)] = d;
    }
}

// --------------- layer-1 aggregation: warp per dst, single pass ---------------
__global__ __launch_bounds__(256) void agg1_kernel(const float* __restrict__ b1, int n) {
    int tid = threadIdx.x;
    int warp = tid >> 5, lane = tid & 31;
    int d = blockIdx.x * 8 + warp;
    if (d >= n) return;
    int h = lane >> 2;
    float ald = g_ald1[d * HEADS + h];
    int beg = g_rowptr[d];
    int cnt = g_cnt[d];
    const int* srcs = g_csr_src + beg;
    float ax = 0.f, ay = 0.f, az = 0.f, aw = 0.f, den = 0.f;
    for (int j = 0; j < cnt; j++) {
        int s = __ldg(srcs + j);
        float e = lrelu(g_als1[s * HEADS + h] + ald);
        float w = __expf(e);
        float4 hv = *(const float4*)(g_h1 + (size_t)s * F1 + lane * 4);
        ax += w * hv.x; ay += w * hv.y; az += w * hv.z; aw += w * hv.w;
        den += w;
    }
    float inv = 1.f / (den + 1e-16f);
    float4 bb = *(const float4*)(b1 + lane * 4);
    float4 o;
    o.x = fmaxf(ax * inv + bb.x, 0.f);
    o.y = fmaxf(ay * inv + bb.y, 0.f);
    o.z = fmaxf(az * inv + bb.z, 0.f);
    o.w = fmaxf(aw * inv + bb.w, 0.f);
    *(float4*)(g_out1 + (size_t)d * F1 + lane * 4) = o;
}

// --------------- GEMM2 + layer-2 logits fused: warp per node ------------------
__global__ __launch_bounds__(256) void gemm2_kernel(const float* __restrict__ W2,
                                                    const float* __restrict__ as2,
                                                    const float* __restrict__ ad2, int n) {
    __shared__ float Ws[F1 * OUT_C];
    __shared__ float sa[OUT_C], sb[OUT_C];
    int tid = threadIdx.x;
    for (int i = tid; i < F1 * OUT_C; i += 256) Ws[i] = W2[i];
    if (tid < OUT_C) { sa[tid] = as2[tid]; sb[tid] = ad2[tid]; }
    __syncthreads();
    int warp = tid >> 5, lane = tid & 31;
    for (int node = blockIdx.x * 8 + warp; node < n; node += gridDim.x * 8) {
        const float* hp = g_out1 + (size_t)node * F1;
        float acc = 0.f;
#pragma unroll
        for (int k0 = 0; k0 < F1; k0 += 4) {
            float4 hv = *(const float4*)(hp + k0);
            acc += hv.x * Ws[(k0 + 0) * OUT_C + lane];
            acc += hv.y * Ws[(k0 + 1) * OUT_C + lane];
            acc += hv.z * Ws[(k0 + 2) * OUT_C + lane];
            acc += hv.w * Ws[(k0 + 3) * OUT_C + lane];
        }
        g_h2[(size_t)node * OUT_C + lane] = acc;
        float s = acc * sa[lane];
        float d2 = acc * sb[lane];
#pragma unroll
        for (int o = 16; o; o >>= 1) {
            s  += __shfl_xor_sync(0xffffffffu, s, o);
            d2 += __shfl_xor_sync(0xffffffffu, d2, o);
        }
        if (lane == 0) { g_als2[node] = s; g_ald2[node] = d2; }
    }
}

// --------------- layer-2 aggregation + bias + log_softmax fused ---------------
__global__ __launch_bounds__(256) void agg2_kernel(const float* __restrict__ b2,
                                                   float* __restrict__ out, int n) {
    int tid = threadIdx.x;
    int warp = tid >> 5, lane = tid & 31;
    int d = blockIdx.x * 8 + warp;
    if (d >= n) return;
    float ald = g_ald2[d];
    int beg = g_rowptr[d];
    int cnt = g_cnt[d];
    const int* srcs = g_csr_src + beg;
    float acc = 0.f, den = 0.f;
    for (int j = 0; j < cnt; j++) {
        int s = __ldg(srcs + j);
        float e = lrelu(g_als2[s] + ald);
        float w = __expf(e);
        acc += w * g_h2[(size_t)s * OUT_C + lane];
        den += w;
    }
    float v = acc / (den + 1e-16f) + b2[lane];
    float mx = v;
#pragma unroll
    for (int o = 16; o; o >>= 1) mx = fmaxf(mx, __shfl_xor_sync(0xffffffffu, mx, o));
    float ex = __expf(v - mx);
    float sum = ex;
#pragma unroll
    for (int o = 16; o; o >>= 1) sum += __shfl_xor_sync(0xffffffffu, sum, o);
    out[(size_t)d * OUT_C + lane] = v - mx - logf(sum);
}

// --------------- launcher ------------------------------------------------------
extern "C" void kernel_launch(void* const* d_in, const int* in_sizes, int n_in,
                              void* d_out, int out_size) {
    const float* x   = (const float*)d_in[0];
    const void*  ei  = d_in[1];
    const float* W1  = (const float*)d_in[2];
    const float* as1 = (const float*)d_in[3];
    const float* ad1 = (const float*)d_in[4];
    const float* b1  = (const float*)d_in[5];
    const float* W2  = (const float*)d_in[6];
    const float* as2 = (const float*)d_in[7];
    const float* ad2 = (const float*)d_in[8];
    const float* b2  = (const float*)d_in[9];

    int n  = in_sizes[0] / IN_C;
    int E  = in_sizes[1] / 2;
    int Et = E + n;
    int nb1024 = (n + 1023) / 1024;

    detect_kernel<<<1, 32>>>((const int*)ei);
    zero_cnt_kernel<<<(n + 255) / 256, 256>>>(n);
    prep_kernel<<<(Et + 255) / 256, 256>>>(ei, E, Et);
    scan1_kernel<<<nb1024, 1024>>>(n);
    scan2_kernel<<<1, 64>>>(nb1024);
    scan3_kernel<<<(n + 255) / 256, 256>>>(n);
    bucket_kernel<<<(Et + 255) / 256, 256>>>(Et);

    gemm1_kernel<<<(n + BM - 1) / BM, 256>>>(x, W1, n);
    node1_kernel<<<(n + 7) / 8, 256>>>(as1, ad1, n);
    agg1_kernel<<<(n + 7) / 8, 256>>>(b1, n);

    gemm2_kernel<<<784, 256>>>(W2, as2, ad2, n);
    agg2_kernel<<<(n + 7) / 8, 256>>>(b2, (float*)d_out, n);
}

// round 3
// speedup vs baseline: 2.4340x; 1.3065x over previous
#include <cuda_runtime.h>
#include <cstdint>

#define IN_C    256
#define HID     16
#define HEADS   8
#define F1      128     // HEADS*HID
#define OUT_C   32
#define SLOPE   0.2f
#define N_MAX   50048
#define E_MAX   851968  // E + N headroom

// ---------------- scratch (device globals; no allocation allowed) ----------
__device__ int2     g_edges  [E_MAX];
__device__ int      g_csr_src[E_MAX];
__device__ int      g_cnt    [N_MAX];
__device__ int      g_rowptr [N_MAX];
__device__ int      g_cursor [N_MAX];
__device__ int      g_bsum   [64];
__device__ float    g_h1  [(size_t)N_MAX * F1];
__device__ float    g_out1[(size_t)N_MAX * F1];
__device__ float    g_als1[(size_t)N_MAX * HEADS];
__device__ float    g_ald1[(size_t)N_MAX * HEADS];
__device__ float    g_h2  [(size_t)N_MAX * OUT_C];
__device__ float    g_als2[N_MAX];
__device__ float    g_ald2[N_MAX];
__device__ int      g_is64;

__device__ __forceinline__ float lrelu(float v) { return v > 0.f ? v : SLOPE * v; }

// --------------- init: zero counters + dtype detection ----------------------
__global__ void init_kernel(const int* ei, int n) {
    int i = blockIdx.x * blockDim.x + threadIdx.x;
    if (i < n) g_cnt[i] = 0;
    if (i == 0) {
        int all0 = 1;
        for (int k = 1; k < 64; k += 2) all0 &= (ei[k] == 0);
        g_is64 = all0;
    }
}

// --------------- edge decode + degree histogram ------------------------------
__global__ void prep_kernel(const void* ei, int E, int Et) {
    int e = blockIdx.x * blockDim.x + threadIdx.x;
    if (e >= Et) return;
    int s, d;
    if (e < E) {
        if (g_is64) {
            const long long* p = (const long long*)ei;
            s = (int)__ldg(p + e); d = (int)__ldg(p + (size_t)E + e);
        } else {
            const int* p = (const int*)ei;
            s = __ldg(p + e); d = __ldg(p + (size_t)E + e);
        }
    } else {
        s = d = e - E;
    }
    g_edges[e] = make_int2(s, d);
    atomicAdd(&g_cnt[d], 1);
}

// --------------- 3-kernel exclusive scan of g_cnt ----------------------------
__global__ __launch_bounds__(1024) void scan1_kernel(int n) {
    __shared__ int sm[1024];
    int i = blockIdx.x * 1024 + threadIdx.x;
    int v = (i < n) ? g_cnt[i] : 0;
    sm[threadIdx.x] = v;
    __syncthreads();
    for (int off = 1; off < 1024; off <<= 1) {
        int t = (threadIdx.x >= off) ? sm[threadIdx.x - off] : 0;
        __syncthreads();
        sm[threadIdx.x] += t;
        __syncthreads();
    }
    if (i < n) g_rowptr[i] = sm[threadIdx.x];      // inclusive (block-local)
    if (threadIdx.x == 1023) g_bsum[blockIdx.x] = sm[1023];
}
__global__ void scan2_kernel(int nb) {
    __shared__ int sm[64];
    int v = (threadIdx.x < nb) ? g_bsum[threadIdx.x] : 0;
    sm[threadIdx.x] = v;
    __syncthreads();
    for (int off = 1; off < 64; off <<= 1) {
        int t = (threadIdx.x >= off) ? sm[threadIdx.x - off] : 0;
        __syncthreads();
        sm[threadIdx.x] += t;
        __syncthreads();
    }
    g_bsum[threadIdx.x] = sm[threadIdx.x];
}
__global__ void scan3_kernel(int n) {
    int i = blockIdx.x * blockDim.x + threadIdx.x;
    if (i >= n) return;
    int b = i >> 10;
    int incl = g_rowptr[i] + (b ? g_bsum[b - 1] : 0);
    int start = incl - g_cnt[i];
    g_rowptr[i] = start;
    g_cursor[i] = start;
}

// --------------- bucket edges by dst ----------------------------------------
__global__ void bucket_kernel(int Et) {
    int e = blockIdx.x * blockDim.x + threadIdx.x;
    if (e >= Et) return;
    int2 sd = g_edges[e];
    int pos = atomicAdd(&g_cursor[sd.y], 1);
    g_csr_src[pos] = sd.x;
}

// --------------- GEMM1 via tf32 mma: h1 = x[M,256] @ W1[256,128] ------------
#define AS_STRIDE 20
#define BS_STRIDE 132
#define ASZ (128 * AS_STRIDE)
#define BSZ (16 * BS_STRIDE)

__device__ __forceinline__ unsigned sptr(const void* p) {
    return (unsigned)__cvta_generic_to_shared(p);
}
__device__ __forceinline__ void cpa16(unsigned dst, const void* src, int pbytes) {
    asm volatile("cp.async.ca.shared.global [%0], [%1], 16, %2;"
                 :: "r"(dst), "l"(src), "r"(pbytes));
}
__device__ __forceinline__ void cp_commit() {
    asm volatile("cp.async.commit_group;");
}
template <int NN> __device__ __forceinline__ void cp_wait() {
    asm volatile("cp.async.wait_group %0;" :: "n"(NN));
}
__device__ __forceinline__ void mma_tf32(float* c, const float* a, const float* b) {
    asm volatile(
        "mma.sync.aligned.m16n8k8.row.col.f32.tf32.tf32.f32 "
        "{%0,%1,%2,%3}, {%4,%5,%6,%7}, {%8,%9}, {%0,%1,%2,%3};"
        : "+f"(c[0]), "+f"(c[1]), "+f"(c[2]), "+f"(c[3])
        : "r"(__float_as_uint(a[0])), "r"(__float_as_uint(a[1])),
          "r"(__float_as_uint(a[2])), "r"(__float_as_uint(a[3])),
          "r"(__float_as_uint(b[0])), "r"(__float_as_uint(b[1])));
}

__global__ __launch_bounds__(256) void gemm1_kernel(const float* __restrict__ A,
                                                    const float* __restrict__ B, int M) {
    __shared__ float As[2][ASZ];
    __shared__ float Bs[2][BSZ];
    int tid = threadIdx.x;
    int warp = tid >> 5, lane = tid & 31;
    int warp_m = warp >> 1, warp_n = warp & 1;     // 4x2 warps: 32x64 per warp
    int row0 = blockIdx.x * 128;

    int lrow = tid >> 1;                 // A load: 0..127
    int lcb  = (tid & 1) * 8;            // col base 0 or 8
    int lk   = tid >> 4;                 // B load: 0..15
    int lnb  = (tid & 15) * 8;

    float acc[2][8][4];
#pragma unroll
    for (int i = 0; i < 2; i++)
#pragma unroll
        for (int j = 0; j < 8; j++)
#pragma unroll
            for (int q = 0; q < 4; q++) acc[i][j][q] = 0.f;

    int apb = (row0 + lrow < M) ? 16 : 0;

    // prologue: load tile 0
    {
        unsigned da = sptr(&As[0][lrow * AS_STRIDE + lcb]);
        cpa16(da,      A + (size_t)(row0 + lrow) * IN_C + lcb, apb);
        cpa16(da + 16, A + (size_t)(row0 + lrow) * IN_C + lcb + 4, apb);
        unsigned db = sptr(&Bs[0][lk * BS_STRIDE + lnb]);
        cpa16(db,      B + (size_t)lk * F1 + lnb, 16);
        cpa16(db + 16, B + (size_t)lk * F1 + lnb + 4, 16);
        cp_commit();
    }

    int r = lane >> 2, c = lane & 3;
#pragma unroll 1
    for (int t = 0; t < 16; t++) {
        int buf = t & 1;
        if (t < 15) {
            int k0 = (t + 1) * 16;
            unsigned da = sptr(&As[buf ^ 1][lrow * AS_STRIDE + lcb]);
            cpa16(da,      A + (size_t)(row0 + lrow) * IN_C + k0 + lcb, apb);
            cpa16(da + 16, A + (size_t)(row0 + lrow) * IN_C + k0 + lcb + 4, apb);
            unsigned db = sptr(&Bs[buf ^ 1][lk * BS_STRIDE + lnb]);
            cpa16(db,      B + (size_t)(k0 + lk) * F1 + lnb, 16);
            cpa16(db + 16, B + (size_t)(k0 + lk) * F1 + lnb + 4, 16);
            cp_commit();
            cp_wait<1>();
        } else {
            cp_wait<0>();
        }
        __syncthreads();

        const float* as = As[buf];
        const float* bs = Bs[buf];
#pragma unroll
        for (int ks = 0; ks < 2; ks++) {
            int k8 = ks * 8;
            float af[2][4];
#pragma unroll
            for (int mf = 0; mf < 2; mf++) {
                int rb = warp_m * 32 + mf * 16 + r;
                af[mf][0] = as[rb * AS_STRIDE + k8 + c];
                af[mf][1] = as[(rb + 8) * AS_STRIDE + k8 + c];
                af[mf][2] = as[rb * AS_STRIDE + k8 + c + 4];
                af[mf][3] = as[(rb + 8) * AS_STRIDE + k8 + c + 4];
            }
            float bf[8][2];
#pragma unroll
            for (int nf = 0; nf < 8; nf++) {
                int nn = warp_n * 64 + nf * 8 + r;
                bf[nf][0] = bs[(k8 + c) * BS_STRIDE + nn];
                bf[nf][1] = bs[(k8 + c + 4) * BS_STRIDE + nn];
            }
#pragma unroll
            for (int mf = 0; mf < 2; mf++)
#pragma unroll
                for (int nf = 0; nf < 8; nf++)
                    mma_tf32(acc[mf][nf], af[mf], bf[nf]);
        }
        __syncthreads();
    }

    // epilogue
#pragma unroll
    for (int mf = 0; mf < 2; mf++) {
        int rA = row0 + warp_m * 32 + mf * 16 + r;
#pragma unroll
        for (int nf = 0; nf < 8; nf++) {
            int cb = warp_n * 64 + nf * 8 + c * 2;
            *(float2*)(g_h1 + (size_t)rA * F1 + cb)       = make_float2(acc[mf][nf][0], acc[mf][nf][1]);
            *(float2*)(g_h1 + (size_t)(rA + 8) * F1 + cb) = make_float2(acc[mf][nf][2], acc[mf][nf][3]);
        }
    }
}

// --------------- layer-1 attention logits: warp per node ---------------------
__global__ __launch_bounds__(256) void node1_kernel(const float* __restrict__ a_src,
                                                    const float* __restrict__ a_dst, int n) {
    __shared__ float ssrc[F1], sdst[F1];
    int tid = threadIdx.x;
    if (tid < F1) { ssrc[tid] = a_src[tid]; sdst[tid] = a_dst[tid]; }
    __syncthreads();
    int warp = tid >> 5, lane = tid & 31;
    int node = blockIdx.x * 8 + warp;
    if (node >= n) return;
    float4 hv = *(const float4*)(g_h1 + (size_t)node * F1 + lane * 4);
    float4 a  = *(const float4*)(ssrc + lane * 4);
    float4 b  = *(const float4*)(sdst + lane * 4);
    float s = hv.x * a.x + hv.y * a.y + hv.z * a.z + hv.w * a.w;
    float d = hv.x * b.x + hv.y * b.y + hv.z * b.z + hv.w * b.w;
    s += __shfl_xor_sync(0xffffffffu, s, 1);
    s += __shfl_xor_sync(0xffffffffu, s, 2);
    d += __shfl_xor_sync(0xffffffffu, d, 1);
    d += __shfl_xor_sync(0xffffffffu, d, 2);
    if ((lane & 3) == 0) {
        g_als1[node * HEADS + (lane >> 2)] = s;
        g_ald1[node * HEADS + (lane >> 2)] = d;
    }
}

// --------------- layer-1 aggregation: warp per dst, pipelined -----------------
__global__ __launch_bounds__(256) void agg1_kernel(const float* __restrict__ b1, int n) {
    int tid = threadIdx.x;
    int warp = tid >> 5, lane = tid & 31;
    int d = blockIdx.x * 8 + warp;
    if (d >= n) return;
    int h = lane >> 2;
    float ald = g_ald1[d * HEADS + h];
    int beg = g_rowptr[d];
    int cnt = g_cnt[d];
    const int* srcs = g_csr_src + beg;
    float ax = 0.f, ay = 0.f, az = 0.f, aw = 0.f, den = 0.f;
    int j = 0;
    for (; j + 4 <= cnt; j += 4) {
        int s0 = __ldg(srcs + j + 0);
        int s1 = __ldg(srcs + j + 1);
        int s2 = __ldg(srcs + j + 2);
        int s3 = __ldg(srcs + j + 3);
        float l0 = __ldg(g_als1 + s0 * HEADS + h);
        float l1 = __ldg(g_als1 + s1 * HEADS + h);
        float l2 = __ldg(g_als1 + s2 * HEADS + h);
        float l3 = __ldg(g_als1 + s3 * HEADS + h);
        float4 v0 = *(const float4*)(g_h1 + (size_t)s0 * F1 + lane * 4);
        float4 v1 = *(const float4*)(g_h1 + (size_t)s1 * F1 + lane * 4);
        float4 v2 = *(const float4*)(g_h1 + (size_t)s2 * F1 + lane * 4);
        float4 v3 = *(const float4*)(g_h1 + (size_t)s3 * F1 + lane * 4);
        float w0 = __expf(lrelu(l0 + ald));
        float w1 = __expf(lrelu(l1 + ald));
        float w2 = __expf(lrelu(l2 + ald));
        float w3 = __expf(lrelu(l3 + ald));
        ax += w0 * v0.x + w1 * v1.x + w2 * v2.x + w3 * v3.x;
        ay += w0 * v0.y + w1 * v1.y + w2 * v2.y + w3 * v3.y;
        az += w0 * v0.z + w1 * v1.z + w2 * v2.z + w3 * v3.z;
        aw += w0 * v0.w + w1 * v1.w + w2 * v2.w + w3 * v3.w;
        den += (w0 + w1) + (w2 + w3);
    }
    for (; j < cnt; j++) {
        int s = __ldg(srcs + j);
        float w = __expf(lrelu(__ldg(g_als1 + s * HEADS + h) + ald));
        float4 v = *(const float4*)(g_h1 + (size_t)s * F1 + lane * 4);
        ax += w * v.x; ay += w * v.y; az += w * v.z; aw += w * v.w;
        den += w;
    }
    float inv = 1.f / (den + 1e-16f);
    float4 bb = *(const float4*)(b1 + lane * 4);
    float4 o;
    o.x = fmaxf(ax * inv + bb.x, 0.f);
    o.y = fmaxf(ay * inv + bb.y, 0.f);
    o.z = fmaxf(az * inv + bb.z, 0.f);
    o.w = fmaxf(aw * inv + bb.w, 0.f);
    *(float4*)(g_out1 + (size_t)d * F1 + lane * 4) = o;
}

// --------------- GEMM2 + layer-2 logits fused: warp per node ------------------
__global__ __launch_bounds__(256) void gemm2_kernel(const float* __restrict__ W2,
                                                    const float* __restrict__ as2,
                                                    const float* __restrict__ ad2, int n) {
    __shared__ float Ws[F1 * OUT_C];
    __shared__ float sa[OUT_C], sb[OUT_C];
    int tid = threadIdx.x;
    for (int i = tid; i < F1 * OUT_C; i += 256) Ws[i] = W2[i];
    if (tid < OUT_C) { sa[tid] = as2[tid]; sb[tid] = ad2[tid]; }
    __syncthreads();
    int warp = tid >> 5, lane = tid & 31;
    for (int node = blockIdx.x * 8 + warp; node < n; node += gridDim.x * 8) {
        const float* hp = g_out1 + (size_t)node * F1;
        float acc = 0.f;
#pragma unroll
        for (int k0 = 0; k0 < F1; k0 += 4) {
            float4 hv = *(const float4*)(hp + k0);
            acc += hv.x * Ws[(k0 + 0) * OUT_C + lane];
            acc += hv.y * Ws[(k0 + 1) * OUT_C + lane];
            acc += hv.z * Ws[(k0 + 2) * OUT_C + lane];
            acc += hv.w * Ws[(k0 + 3) * OUT_C + lane];
        }
        g_h2[(size_t)node * OUT_C + lane] = acc;
        float s = acc * sa[lane];
        float d2 = acc * sb[lane];
#pragma unroll
        for (int o = 16; o; o >>= 1) {
            s  += __shfl_xor_sync(0xffffffffu, s, o);
            d2 += __shfl_xor_sync(0xffffffffu, d2, o);
        }
        if (lane == 0) { g_als2[node] = s; g_ald2[node] = d2; }
    }
}

// --------------- layer-2 aggregation + bias + log_softmax fused ---------------
__global__ __launch_bounds__(256) void agg2_kernel(const float* __restrict__ b2,
                                                   float* __restrict__ out, int n) {
    int tid = threadIdx.x;
    int warp = tid >> 5, lane = tid & 31;
    int d = blockIdx.x * 8 + warp;
    if (d >= n) return;
    float ald = g_ald2[d];
    int beg = g_rowptr[d];
    int cnt = g_cnt[d];
    const int* srcs = g_csr_src + beg;
    float acc = 0.f, den = 0.f;
    int j = 0;
    for (; j + 4 <= cnt; j += 4) {
        int s0 = __ldg(srcs + j + 0);
        int s1 = __ldg(srcs + j + 1);
        int s2 = __ldg(srcs + j + 2);
        int s3 = __ldg(srcs + j + 3);
        float l0 = __ldg(g_als2 + s0);
        float l1 = __ldg(g_als2 + s1);
        float l2 = __ldg(g_als2 + s2);
        float l3 = __ldg(g_als2 + s3);
        float h0 = __ldg(g_h2 + (size_t)s0 * OUT_C + lane);
        float h1v = __ldg(g_h2 + (size_t)s1 * OUT_C + lane);
        float h2v = __ldg(g_h2 + (size_t)s2 * OUT_C + lane);
        float h3 = __ldg(g_h2 + (size_t)s3 * OUT_C + lane);
        float w0 = __expf(lrelu(l0 + ald));
        float w1 = __expf(lrelu(l1 + ald));
        float w2 = __expf(lrelu(l2 + ald));
        float w3 = __expf(lrelu(l3 + ald));
        acc += w0 * h0 + w1 * h1v + w2 * h2v + w3 * h3;
        den += (w0 + w1) + (w2 + w3);
    }
    for (; j < cnt; j++) {
        int s = __ldg(srcs + j);
        float w = __expf(lrelu(__ldg(g_als2 + s) + ald));
        acc += w * __ldg(g_h2 + (size_t)s * OUT_C + lane);
        den += w;
    }
    float v = acc / (den + 1e-16f) + b2[lane];
    float mx = v;
#pragma unroll
    for (int o = 16; o; o >>= 1) mx = fmaxf(mx, __shfl_xor_sync(0xffffffffu, mx, o));
    float ex = __expf(v - mx);
    float sum = ex;
#pragma unroll
    for (int o = 16; o; o >>= 1) sum += __shfl_xor_sync(0xffffffffu, sum, o);
    out[(size_t)d * OUT_C + lane] = v - mx - logf(sum);
}

// --------------- launcher ------------------------------------------------------
extern "C" void kernel_launch(void* const* d_in, const int* in_sizes, int n_in,
                              void* d_out, int out_size) {
    const float* x   = (const float*)d_in[0];
    const void*  ei  = d_in[1];
    const float* W1  = (const float*)d_in[2];
    const float* as1 = (const float*)d_in[3];
    const float* ad1 = (const float*)d_in[4];
    const float* b1  = (const float*)d_in[5];
    const float* W2  = (const float*)d_in[6];
    const float* as2 = (const float*)d_in[7];
    const float* ad2 = (const float*)d_in[8];
    const float* b2  = (const float*)d_in[9];

    int n  = in_sizes[0] / IN_C;
    int E  = in_sizes[1] / 2;
    int Et = E + n;
    int nb1024 = (n + 1023) / 1024;

    init_kernel<<<(n + 255) / 256, 256>>>((const int*)ei, n);
    prep_kernel<<<(Et + 255) / 256, 256>>>(ei, E, Et);
    scan1_kernel<<<nb1024, 1024>>>(n);
    scan2_kernel<<<1, 64>>>(nb1024);
    scan3_kernel<<<(n + 255) / 256, 256>>>(n);
    bucket_kernel<<<(Et + 255) / 256, 256>>>(Et);

    gemm1_kernel<<<(n + 127) / 128, 256>>>(x, W1, n);
    node1_kernel<<<(n + 7) / 8, 256>>>(as1, ad1, n);
    agg1_kernel<<<(n + 7) / 8, 256>>>(b1, n);

    gemm2_kernel<<<784, 256>>>(W2, as2, ad2, n);
    agg2_kernel<<<(n + 7) / 8, 256>>>(b2, (float*)d_out, n);
}